// round 2
// baseline (speedup 1.0000x reference)
#include <cuda_runtime.h>
#include <cstdint>
#include <cstddef>

// Problem constants
#define S_LEN   2048
#define BATCH   2
#define DIM     512
#define NHEAD   8
#define EDIM    512
#define HE_DIM  (NHEAD * EDIM)

// ---------------------------------------------------------------------------
// Scratch (device globals — no allocation allowed)
// ---------------------------------------------------------------------------
__device__ float g_q[BATCH * NHEAD * S_LEN * EDIM];        // 64 MB  [b,h,s,e]
__device__ float g_k[BATCH * NHEAD * S_LEN * EDIM];        // 64 MB
__device__ float g_v[BATCH * NHEAD * S_LEN * EDIM];        // 64 MB
__device__ float g_attn[(size_t)BATCH * NHEAD * S_LEN * S_LEN]; // 256 MB [b,h,s,t]
__device__ float g_cat[BATCH * S_LEN * HE_DIM];            // 64 MB  [b,s,h*E+e]
__device__ int   g_mask_kind;                              // 0=u8, 1=i32, 2=f32

// ---------------------------------------------------------------------------
// Packed f32x2 helpers (FFMA2 path — 2x fp32 FMA throughput on sm_103a)
// ---------------------------------------------------------------------------
__device__ __forceinline__ unsigned long long pk2(float lo, float hi) {
    unsigned long long r;
    asm("mov.b64 %0, {%1, %2};" : "=l"(r) : "f"(lo), "f"(hi));
    return r;
}
__device__ __forceinline__ void fma2(unsigned long long& acc,
                                     unsigned long long a,
                                     unsigned long long b) {
    asm("fma.rn.f32x2 %0, %1, %2, %0;" : "+l"(acc) : "l"(a), "l"(b));
}
__device__ __forceinline__ float2 upk2(unsigned long long v) {
    float2 f;
    asm("mov.b64 {%0, %1}, %2;" : "=f"(f.x), "=f"(f.y) : "l"(v));
    return f;
}

// ---------------------------------------------------------------------------
// Mask dtype detection: bool may be delivered as uint8, int32, or float32.
// Random 0/1 data makes the three cases unambiguous over 256 words
// (misclassification probability ~2^-256). Deterministic per input.
// ---------------------------------------------------------------------------
__global__ void detect_mask_kind(const void* __restrict__ mask) {
    const unsigned int* w = (const unsigned int*)mask;
    bool all01 = true, allf = true;
    for (int i = 0; i < 256; i++) {
        unsigned int x = w[i];
        if (x > 1u) all01 = false;
        if (x != 0u && x != 0x3F800000u) allf = false;
    }
    g_mask_kind = all01 ? 1 : (allf ? 2 : 0);
}

// ---------------------------------------------------------------------------
// Generic 128x128x8 fp32 SIMT GEMM, 256 threads, 8x8 micro-tile per thread,
// packed-f32x2 accumulation. All dims are multiples of 128/8 in this problem,
// so no bounds guards. A is [M,K] row-major (lda=K always here).
//   TRANS_B=false: B is [K,N] row-major (ldb=N).
//   TRANS_B=true : B is [N,K] row-major (C = A @ B^T).
// Batch handling:
//   A offset = (z / aDiv) * aBatch     (aDiv=NHEAD for projections: A shared per b)
//   B offset = (z % bMod) * bBatch     (bMod=NHEAD for projections: W per head)
// biasMode: 0 none, 1 bias + (z%NHEAD)*EDIM, 2 bias (single)
// cMode:    0 C = Call + z*M*N, ldc=N
//           1 (PV->concat) C = Call + (z/NHEAD)*S_LEN*HE_DIM + (z%NHEAD)*EDIM, ldc=HE_DIM
// ---------------------------------------------------------------------------
template <bool TRANS_B>
__global__ __launch_bounds__(256, 2)
void gemm128(const float* __restrict__ Aall, const float* __restrict__ Ball,
             const float* __restrict__ biasAll, float* __restrict__ Call,
             int M, int N, int K,
             long aBatch, int aDiv, long bBatch, int bMod,
             int biasMode, int cMode) {
    const int z = blockIdx.z;
    const float* A = Aall + (size_t)(z / aDiv) * (size_t)aBatch;
    const float* B = Ball + (size_t)(z % bMod) * (size_t)bBatch;

    float* C;
    int ldc;
    if (cMode == 0) {
        C = Call + (size_t)z * (size_t)M * (size_t)N;
        ldc = N;
    } else {
        const int b = z / NHEAD, h = z % NHEAD;
        C = Call + (size_t)b * S_LEN * HE_DIM + (size_t)h * EDIM;
        ldc = HE_DIM;
    }
    const float* bias = nullptr;
    if (biasMode == 1)      bias = biasAll + (size_t)(z % NHEAD) * EDIM;
    else if (biasMode == 2) bias = biasAll;

    __shared__ __align__(16) float As[8][128];
    __shared__ __align__(16) float Bs[8][128];

    const int tid = threadIdx.x;
    const int tx = tid & 15;        // 0..15 -> 8 output cols each
    const int ty = tid >> 4;        // 0..15 -> 8 output rows each
    const int row0 = blockIdx.y * 128;
    const int col0 = blockIdx.x * 128;

    // A-tile / transposed-B-tile loader coords (float4 per thread)
    const int aRow = tid >> 1;              // 0..127
    const int aCol = (tid & 1) * 4;         // 0 or 4
    // non-transposed B loader coords
    const int bRow = tid >> 5;              // 0..7
    const int bCol = (tid & 31) * 4;        // 0..124

    unsigned long long acc[8][4];
#pragma unroll
    for (int i = 0; i < 8; i++)
#pragma unroll
        for (int j = 0; j < 4; j++) acc[i][j] = 0ull;

    for (int k0 = 0; k0 < K; k0 += 8) {
        const float4 aR = *(const float4*)&A[(size_t)(row0 + aRow) * K + k0 + aCol];
        float4 bR;
        if (TRANS_B)
            bR = *(const float4*)&B[(size_t)(col0 + aRow) * K + k0 + aCol];
        else
            bR = *(const float4*)&B[(size_t)(k0 + bRow) * N + col0 + bCol];

        __syncthreads();
        As[aCol + 0][aRow] = aR.x;
        As[aCol + 1][aRow] = aR.y;
        As[aCol + 2][aRow] = aR.z;
        As[aCol + 3][aRow] = aR.w;
        if (TRANS_B) {
            Bs[aCol + 0][aRow] = bR.x;
            Bs[aCol + 1][aRow] = bR.y;
            Bs[aCol + 2][aRow] = bR.z;
            Bs[aCol + 3][aRow] = bR.w;
        } else {
            *(float4*)&Bs[bRow][bCol] = bR;
        }
        __syncthreads();

#pragma unroll
        for (int kk = 0; kk < 8; kk++) {
            const float4 a0 = *(const float4*)&As[kk][ty * 8];
            const float4 a1 = *(const float4*)&As[kk][ty * 8 + 4];
            const float4 b0 = *(const float4*)&Bs[kk][tx * 8];
            const float4 b1 = *(const float4*)&Bs[kk][tx * 8 + 4];
            const unsigned long long bb0 = pk2(b0.x, b0.y);
            const unsigned long long bb1 = pk2(b0.z, b0.w);
            const unsigned long long bb2 = pk2(b1.x, b1.y);
            const unsigned long long bb3 = pk2(b1.z, b1.w);
            const float av[8] = {a0.x, a0.y, a0.z, a0.w, a1.x, a1.y, a1.z, a1.w};
#pragma unroll
            for (int i = 0; i < 8; i++) {
                const unsigned long long aa = pk2(av[i], av[i]);
                fma2(acc[i][0], aa, bb0);
                fma2(acc[i][1], aa, bb1);
                fma2(acc[i][2], aa, bb2);
                fma2(acc[i][3], aa, bb3);
            }
        }
    }

    // Epilogue
    const int ccol = col0 + tx * 8;
#pragma unroll
    for (int i = 0; i < 8; i++) {
        const size_t r = (size_t)(row0 + ty * 8 + i);
        float o[8];
#pragma unroll
        for (int j = 0; j < 4; j++) {
            const float2 f = upk2(acc[i][j]);
            o[2 * j] = f.x;
            o[2 * j + 1] = f.y;
        }
        if (biasMode) {
#pragma unroll
            for (int j = 0; j < 8; j++) o[j] += bias[ccol + j];
        }
        float4* cp = (float4*)(C + r * (size_t)ldc + ccol);
        cp[0] = make_float4(o[0], o[1], o[2], o[3]);
        cp[1] = make_float4(o[4], o[5], o[6], o[7]);
    }
}

// ---------------------------------------------------------------------------
// Masked softmax over the last dim of g_attn, in place.
// One block (256 threads) per row of length S_LEN=2048 (8 elems/thread).
// mask[b, s, t] broadcast over heads; masked -> -1e9 before softmax
// (fully-masked rows correctly become uniform, matching jax).
// ---------------------------------------------------------------------------
__global__ void masked_softmax_kernel(const void* __restrict__ mask) {
    const int z = blockIdx.x;                   // z = (b*NHEAD + h)*S_LEN + s
    const int b = z / (NHEAD * S_LEN);
    const int s = z % S_LEN;
    float* row = g_attn + (size_t)z * S_LEN;
    const size_t mbase = (size_t)b * S_LEN * S_LEN + (size_t)s * S_LEN;
    const int kind = g_mask_kind;
    const int tid = threadIdx.x;

    float v[8];
    float mx = -3.0e38f;
#pragma unroll
    for (int i = 0; i < 8; i++) {
        const int t = tid + i * 256;
        bool mk;
        if (kind == 1)      mk = ((const int*)mask)[mbase + t] != 0;
        else if (kind == 2) mk = ((const float*)mask)[mbase + t] != 0.0f;
        else                mk = ((const unsigned char*)mask)[mbase + t] != 0;
        const float x = mk ? row[t] : -1.0e9f;
        v[i] = x;
        mx = fmaxf(mx, x);
    }

    __shared__ float sm[256];
    sm[tid] = mx;
    __syncthreads();
    for (int o = 128; o > 0; o >>= 1) {
        if (tid < o) sm[tid] = fmaxf(sm[tid], sm[tid + o]);
        __syncthreads();
    }
    mx = sm[0];
    __syncthreads();

    float sum = 0.0f;
#pragma unroll
    for (int i = 0; i < 8; i++) {
        v[i] = __expf(v[i] - mx);
        sum += v[i];
    }
    sm[tid] = sum;
    __syncthreads();
    for (int o = 128; o > 0; o >>= 1) {
        if (tid < o) sm[tid] += sm[tid + o];
        __syncthreads();
    }
    const float inv = 1.0f / sm[0];
#pragma unroll
    for (int i = 0; i < 8; i++) row[tid + i * 256] = v[i] * inv;
}

// ---------------------------------------------------------------------------
// Launcher
// ---------------------------------------------------------------------------
extern "C" void kernel_launch(void* const* d_in, const int* in_sizes, int n_in,
                              void* d_out, int out_size) {
    (void)in_sizes; (void)n_in; (void)out_size;

    const float* query = (const float*)d_in[0];
    const float* key   = (const float*)d_in[1];
    const float* value = (const float*)d_in[2];
    const void*  mask  = d_in[3];
    const float* Wq = (const float*)d_in[4];
    const float* bq = (const float*)d_in[5];
    const float* Wk = (const float*)d_in[6];
    const float* bk = (const float*)d_in[7];
    const float* Wv = (const float*)d_in[8];
    const float* bv = (const float*)d_in[9];
    const float* Wo = (const float*)d_in[10];
    const float* bo = (const float*)d_in[11];
    float* out = (float*)d_out;

    void *qp_, *kp_, *vp_, *ap_, *cp_;
    cudaGetSymbolAddress(&qp_, g_q);
    cudaGetSymbolAddress(&kp_, g_k);
    cudaGetSymbolAddress(&vp_, g_v);
    cudaGetSymbolAddress(&ap_, g_attn);
    cudaGetSymbolAddress(&cp_, g_cat);
    float* qp = (float*)qp_;
    float* kp = (float*)kp_;
    float* vp = (float*)vp_;
    float* ap = (float*)ap_;
    float* cp = (float*)cp_;

    const int BIG = 1 << 30;

    detect_mask_kind<<<1, 1>>>(mask);

    // 1) Projections: [S,D] @ [D,E] + bias -> g_{q,k,v}[b,h,s,e], z = b*H+h
    {
        dim3 grid(EDIM / 128, S_LEN / 128, BATCH * NHEAD);
        gemm128<false><<<grid, 256>>>(query, Wq, bq, qp, S_LEN, EDIM, DIM,
                                      (long)S_LEN * DIM, NHEAD,
                                      (long)DIM * EDIM, NHEAD, 1, 0);
        gemm128<false><<<grid, 256>>>(key, Wk, bk, kp, S_LEN, EDIM, DIM,
                                      (long)S_LEN * DIM, NHEAD,
                                      (long)DIM * EDIM, NHEAD, 1, 0);
        gemm128<false><<<grid, 256>>>(value, Wv, bv, vp, S_LEN, EDIM, DIM,
                                      (long)S_LEN * DIM, NHEAD,
                                      (long)DIM * EDIM, NHEAD, 1, 0);
    }

    // 2) Scores: q[S,E] @ k[S,E]^T -> g_attn[b,h,S,S]
    {
        dim3 grid(S_LEN / 128, S_LEN / 128, BATCH * NHEAD);
        gemm128<true><<<grid, 256>>>(qp, kp, nullptr, ap, S_LEN, S_LEN, EDIM,
                                     (long)S_LEN * EDIM, 1,
                                     (long)S_LEN * EDIM, BIG, 0, 0);
    }

    // 3) Masked softmax in place
    masked_softmax_kernel<<<BATCH * NHEAD * S_LEN, 256>>>(mask);

    // 4) PV: attn[S,S] @ v[S,E] -> concat layout g_cat[b,s,h*E+e]
    {
        dim3 grid(EDIM / 128, S_LEN / 128, BATCH * NHEAD);
        gemm128<false><<<grid, 256>>>(ap, vp, nullptr, cp, S_LEN, EDIM, S_LEN,
                                      (long)S_LEN * S_LEN, 1,
                                      (long)S_LEN * EDIM, BIG, 0, 1);
    }

    // 5) Output projection: cat[B*S, H*E] @ Wo[H*E, E] + bo -> out[B,S,E]
    {
        dim3 grid(EDIM / 128, (BATCH * S_LEN) / 128, 1);
        gemm128<false><<<grid, 256>>>(cp, Wo, bo, out, BATCH * S_LEN, EDIM,
                                      HE_DIM, 0L, 1, 0L, 1, 2, 0);
    }
}

// round 7
// speedup vs baseline: 2.4404x; 2.4404x over previous
#include <cuda_runtime.h>
#include <cuda_bf16.h>
#include <cstdint>
#include <cstddef>

// Problem constants
#define S_LEN   2048
#define BATCH   2
#define DIM     512
#define NHEAD   8
#define EDIM    512
#define HE_DIM  (NHEAD * EDIM)

// GEMM tile config
#define TM 128
#define TN 128
#define KC 64                         // bf16 elems per k-chunk (128B rows, SW128)
#define TILEB (TM * KC * 2)           // 16384 bytes per operand tile
#define STAGE (4 * TILEB)             // Ah, Al, Bh, Bl
#define SMEM_DYN (2 * STAGE)          // 131072 (epilogue reuses this area)

// ---------------------------------------------------------------------------
// Scratch (device globals — no allocation allowed)
// ---------------------------------------------------------------------------
__device__ __align__(16) __nv_bfloat16 g_xh[3][BATCH * S_LEN * DIM];
__device__ __align__(16) __nv_bfloat16 g_xl[3][BATCH * S_LEN * DIM];
__device__ __align__(16) __nv_bfloat16 g_wth[3][NHEAD * EDIM * DIM];  // W^T per head
__device__ __align__(16) __nv_bfloat16 g_wtl[3][NHEAD * EDIM * DIM];
__device__ __align__(16) __nv_bfloat16 g_woth[EDIM * HE_DIM];
__device__ __align__(16) __nv_bfloat16 g_wotl[EDIM * HE_DIM];
__device__ __align__(16) __nv_bfloat16 g_qh[BATCH * NHEAD * S_LEN * EDIM];
__device__ __align__(16) __nv_bfloat16 g_ql[BATCH * NHEAD * S_LEN * EDIM];
__device__ __align__(16) __nv_bfloat16 g_kh[BATCH * NHEAD * S_LEN * EDIM];
__device__ __align__(16) __nv_bfloat16 g_kl[BATCH * NHEAD * S_LEN * EDIM];
__device__ __align__(16) __nv_bfloat16 g_vth[BATCH * NHEAD * EDIM * S_LEN]; // v^T [e,s]
__device__ __align__(16) __nv_bfloat16 g_vtl[BATCH * NHEAD * EDIM * S_LEN];
__device__ __align__(16) float g_attn[(size_t)BATCH * NHEAD * S_LEN * S_LEN];
__device__ __align__(16) __nv_bfloat16 g_ah[(size_t)BATCH * NHEAD * S_LEN * S_LEN];
__device__ __align__(16) __nv_bfloat16 g_al[(size_t)BATCH * NHEAD * S_LEN * S_LEN];
__device__ __align__(16) __nv_bfloat16 g_cath[BATCH * S_LEN * HE_DIM];
__device__ __align__(16) __nv_bfloat16 g_catl[BATCH * S_LEN * HE_DIM];
__device__ int g_mask_kind;

// ---------------------------------------------------------------------------
// PTX helpers (base sm_103 ISA only: cp.async, ldmatrix, mma.sync)
// ---------------------------------------------------------------------------
__device__ __forceinline__ uint32_t smem_u32(const void* p) {
    uint32_t a;
    asm("{ .reg .u64 t; cvta.to.shared.u64 t, %1; cvt.u32.u64 %0, t; }" : "=r"(a) : "l"(p));
    return a;
}
#define SW128(off) ((off) ^ (((off) >> 3) & 0x70))

#define CP16(sa, gp) asm volatile( \
    "cp.async.cg.shared.global [%0], [%1], 16;" :: "r"(sa), "l"(gp) : "memory")
#define CP_COMMIT() asm volatile("cp.async.commit_group;" ::: "memory")
#define CP_WAIT1() asm volatile("cp.async.wait_group 1;" ::: "memory")
#define CP_WAIT0() asm volatile("cp.async.wait_group 0;" ::: "memory")

#define LDSM4(r, a) asm volatile( \
    "ldmatrix.sync.aligned.m8n8.x4.shared.b16 {%0,%1,%2,%3}, [%4];" \
    : "=r"((r)[0]), "=r"((r)[1]), "=r"((r)[2]), "=r"((r)[3]) : "r"(a))

#define MMA16816(d, a, b0, b1) asm volatile( \
    "mma.sync.aligned.m16n8k16.row.col.f32.bf16.bf16.f32 " \
    "{%0,%1,%2,%3}, {%4,%5,%6,%7}, {%8,%9}, {%0,%1,%2,%3};" \
    : "+f"((d)[0]), "+f"((d)[1]), "+f"((d)[2]), "+f"((d)[3]) \
    : "r"((a)[0]), "r"((a)[1]), "r"((a)[2]), "r"((a)[3]), "r"(b0), "r"(b1))

__device__ __forceinline__ void split2(float v, __nv_bfloat16& h, __nv_bfloat16& l) {
    h = __float2bfloat16(v);
    l = __float2bfloat16(v - __bfloat162float(h));
}

// ---------------------------------------------------------------------------
// Mask dtype detection (bool may arrive as u8 / i32 / f32)
// ---------------------------------------------------------------------------
__global__ void detect_mask_kind(const void* __restrict__ mask) {
    const unsigned int* w = (const unsigned int*)mask;
    bool all01 = true, allf = true;
    for (int i = 0; i < 256; i++) {
        unsigned int x = w[i];
        if (x > 1u) all01 = false;
        if (x != 0u && x != 0x3F800000u) allf = false;
    }
    g_mask_kind = all01 ? 1 : (allf ? 2 : 0);
}

// ---------------------------------------------------------------------------
// Split fp32 -> (hi, lo) bf16, flat
// ---------------------------------------------------------------------------
__global__ void split_flat(const float* __restrict__ src,
                           __nv_bfloat16* __restrict__ hi,
                           __nv_bfloat16* __restrict__ lo, int n) {
    int i = blockIdx.x * blockDim.x + threadIdx.x;
    if (i < n) {
        __nv_bfloat16 h, l;
        split2(src[i], h, l);
        hi[i] = h;
        lo[i] = l;
    }
}

// ---------------------------------------------------------------------------
// Split + transpose: src [Z][R][C] fp32 -> dst [Z][C][R] bf16 hi/lo
// ---------------------------------------------------------------------------
__global__ void split_T(const float* __restrict__ src,
                        __nv_bfloat16* __restrict__ hi,
                        __nv_bfloat16* __restrict__ lo, int R, int C) {
    __shared__ float tile[32][33];
    const int z = blockIdx.z;
    const float* s = src + (size_t)z * R * C;
    __nv_bfloat16* dh = hi + (size_t)z * R * C;
    __nv_bfloat16* dl = lo + (size_t)z * R * C;
    const int c0 = blockIdx.x * 32, r0 = blockIdx.y * 32;
    const int tx = threadIdx.x, ty = threadIdx.y;
#pragma unroll
    for (int i = 0; i < 4; i++)
        tile[ty + i * 8][tx] = s[(size_t)(r0 + ty + i * 8) * C + c0 + tx];
    __syncthreads();
#pragma unroll
    for (int i = 0; i < 4; i++) {
        __nv_bfloat16 h, l;
        split2(tile[tx][ty + i * 8], h, l);
        const size_t idx = (size_t)(c0 + ty + i * 8) * R + r0 + tx;
        dh[idx] = h;
        dl[idx] = l;
    }
}

// ---------------------------------------------------------------------------
// bf16x3 HMMA GEMM: C = A @ B^T (+bias). Both operands K-major as (hi,lo).
// 128x128 tile / CTA, K-chunk 64, cp.async double buffer, mma.sync m16n8k16.
// 8 warps: warpM = wid&1 (64 rows), warpN = wid>>1 (32 cols).
// OM: 0 = fp32 out, 1 = split-bf16 out, 2 = split-bf16 transposed out.
// ---------------------------------------------------------------------------
template <int OM>
__global__ __launch_bounds__(256, 1)
void mm_hmma(const __nv_bfloat16* __restrict__ Ah, const __nv_bfloat16* __restrict__ Al,
             long aBatch, int aDiv, int lda,
             const __nv_bfloat16* __restrict__ Bh, const __nv_bfloat16* __restrict__ Bl,
             long bBatch, int bMod, int ldb,
             const float* __restrict__ biasAll, int biasMode,
             void* __restrict__ C0, __nv_bfloat16* __restrict__ Cl,
             long cBatch, int cMode, int ldc, int K) {
    extern __shared__ char smem[];
    const uint32_t sb = smem_u32(smem);
    const int t = threadIdx.x;
    const int lane = t & 31;
    const int wid = t >> 5;
    const int warpM = wid & 1;
    const int warpN = wid >> 1;
    const int z = blockIdx.z;
    const int row0 = blockIdx.y * TM;
    const int col0 = blockIdx.x * TN;

    const __nv_bfloat16* pAh = Ah + (size_t)(z / aDiv) * (size_t)aBatch;
    const __nv_bfloat16* pAl = Al + (size_t)(z / aDiv) * (size_t)aBatch;
    const __nv_bfloat16* pBh = Bh + (size_t)(z % bMod) * (size_t)bBatch;
    const __nv_bfloat16* pBl = Bl + (size_t)(z % bMod) * (size_t)bBatch;

    float acc[4][4][4] = {};

    auto issue = [&](int c, int buf) {
        const int k0 = c * KC;
        const uint32_t s0 = sb + buf * STAGE;
#pragma unroll
        for (int i = 0; i < 4; i++) {
            const int ch = t + i * 256;           // 1024 16B chunks per tile
            const int r = ch >> 3;                // 0..127
            const int q = (ch & 7) * 8;           // bf16 col
            const uint32_t so = SW128((uint32_t)(r * 128 + q * 2));
            const size_t ao = (size_t)(row0 + r) * lda + k0 + q;
            const size_t bo = (size_t)(col0 + r) * ldb + k0 + q;
            CP16(s0 + so, pAh + ao);
            CP16(s0 + TILEB + so, pAl + ao);
            CP16(s0 + 2 * TILEB + so, pBh + bo);
            CP16(s0 + 3 * TILEB + so, pBl + bo);
        }
    };

    const int arow = lane & 15;
    const int koff = (lane >> 4) * 16;            // byte offset of k half

    auto compute = [&](int buf) {
        const uint32_t s0 = sb + buf * STAGE;
#pragma unroll
        for (int ks = 0; ks < 4; ks++) {
            uint32_t fah[4][4], fal[4][4], fbh[2][4], fbl[2][4];
#pragma unroll
            for (int mt = 0; mt < 4; mt++) {
                const uint32_t off = SW128(
                    (uint32_t)((warpM * 64 + mt * 16 + arow) * 128 + ks * 32 + koff));
                LDSM4(fah[mt], s0 + off);
                LDSM4(fal[mt], s0 + TILEB + off);
            }
#pragma unroll
            for (int p = 0; p < 2; p++) {
                const uint32_t off = SW128(
                    (uint32_t)((warpN * 32 + p * 16 + arow) * 128 + ks * 32 + koff));
                LDSM4(fbh[p], s0 + 2 * TILEB + off);
                LDSM4(fbl[p], s0 + 3 * TILEB + off);
            }
#pragma unroll
            for (int mt = 0; mt < 4; mt++)
#pragma unroll
                for (int nt = 0; nt < 4; nt++) {
                    const int p = nt >> 1, o = nt & 1;
                    MMA16816(acc[mt][nt], fah[mt], fbh[p][o], fbh[p][o + 2]);
                    MMA16816(acc[mt][nt], fah[mt], fbl[p][o], fbl[p][o + 2]);
                    MMA16816(acc[mt][nt], fal[mt], fbh[p][o], fbh[p][o + 2]);
                }
        }
    };

    const int NC = K / KC;
    issue(0, 0);
    CP_COMMIT();
    for (int c = 0; c < NC; c++) {
        if (c + 1 < NC) {
            issue(c + 1, (c + 1) & 1);
            CP_COMMIT();
            CP_WAIT1();
        } else {
            CP_COMMIT();
            CP_WAIT0();
        }
        __syncthreads();
        compute(c & 1);
        __syncthreads();
    }

    // ---------------- Epilogue: accum -> smem -> global ----------------
    float* esm = (float*)smem;                    // [128][132]
#pragma unroll
    for (int mt = 0; mt < 4; mt++)
#pragma unroll
        for (int nt = 0; nt < 4; nt++) {
            const int r = warpM * 64 + mt * 16 + (lane >> 2);
            const int cc = warpN * 32 + nt * 8 + (lane & 3) * 2;
            *(float2*)&esm[r * 132 + cc] = make_float2(acc[mt][nt][0], acc[mt][nt][1]);
            *(float2*)&esm[(r + 8) * 132 + cc] = make_float2(acc[mt][nt][2], acc[mt][nt][3]);
        }
    __syncthreads();

    size_t zoff;
    if (cMode == 0) zoff = (size_t)z * (size_t)cBatch;
    else zoff = (size_t)(z / NHEAD) * S_LEN * HE_DIM + (size_t)(z % NHEAD) * EDIM;
    const float* bias = nullptr;
    if (biasMode == 1) bias = biasAll + (size_t)(z % NHEAD) * EDIM;
    else if (biasMode == 2) bias = biasAll;

    if (OM != 2) {
        const int m = t >> 1, cs = (t & 1) * 64;
#pragma unroll
        for (int jj = 0; jj < 64; jj += 16) {
            float v[16];
#pragma unroll
            for (int j = 0; j < 16; j++) {
                v[j] = esm[m * 132 + cs + jj + j];
                if (biasMode) v[j] += bias[col0 + cs + jj + j];
            }
            const size_t idx = zoff + (size_t)(row0 + m) * ldc + col0 + cs + jj;
            if (OM == 0) {
                float4* dst = (float4*)((float*)C0 + idx);
#pragma unroll
                for (int j = 0; j < 4; j++)
                    dst[j] = make_float4(v[4 * j], v[4 * j + 1], v[4 * j + 2], v[4 * j + 3]);
            } else {
                __align__(16) __nv_bfloat16 hb[16], lb[16];
#pragma unroll
                for (int j = 0; j < 16; j++) split2(v[j], hb[j], lb[j]);
                *(uint4*)((__nv_bfloat16*)C0 + idx) = *(uint4*)hb;
                *(uint4*)((__nv_bfloat16*)C0 + idx + 8) = *(uint4*)(hb + 8);
                *(uint4*)(Cl + idx) = *(uint4*)lb;
                *(uint4*)(Cl + idx + 8) = *(uint4*)(lb + 8);
            }
        }
    } else {
        const int e = t >> 1, m0 = (t & 1) * 64;
        const float bv = biasMode ? bias[col0 + e] : 0.0f;
#pragma unroll
        for (int jj = 0; jj < 64; jj += 16) {
            __align__(16) __nv_bfloat16 hb[16], lb[16];
#pragma unroll
            for (int j = 0; j < 16; j++)
                split2(esm[(m0 + jj + j) * 132 + e] + bv, hb[j], lb[j]);
            const size_t idx = zoff + (size_t)(col0 + e) * ldc + row0 + m0 + jj;
            *(uint4*)((__nv_bfloat16*)C0 + idx) = *(uint4*)hb;
            *(uint4*)((__nv_bfloat16*)C0 + idx + 8) = *(uint4*)(hb + 8);
            *(uint4*)(Cl + idx) = *(uint4*)lb;
            *(uint4*)(Cl + idx + 8) = *(uint4*)(lb + 8);
        }
    }
}

// ---------------------------------------------------------------------------
// Masked softmax: reads fp32 g_attn row, writes split bf16 to g_ah/g_al.
// ---------------------------------------------------------------------------
__global__ void masked_softmax_split(const void* __restrict__ mask) {
    const int z = blockIdx.x;
    const int b = z / (NHEAD * S_LEN);
    const int s = z % S_LEN;
    const float* row = g_attn + (size_t)z * S_LEN;
    __nv_bfloat16* oh = g_ah + (size_t)z * S_LEN;
    __nv_bfloat16* ol = g_al + (size_t)z * S_LEN;
    const size_t mbase = (size_t)b * S_LEN * S_LEN + (size_t)s * S_LEN;
    const int kind = g_mask_kind;
    const int tid = threadIdx.x;

    float v[8];
    float mx = -3.0e38f;
#pragma unroll
    for (int i = 0; i < 8; i++) {
        const int tt = tid + i * 256;
        bool mk;
        if (kind == 1)      mk = ((const int*)mask)[mbase + tt] != 0;
        else if (kind == 2) mk = ((const float*)mask)[mbase + tt] != 0.0f;
        else                mk = ((const unsigned char*)mask)[mbase + tt] != 0;
        const float x = mk ? row[tt] : -1.0e9f;
        v[i] = x;
        mx = fmaxf(mx, x);
    }
    __shared__ float sm[256];
    sm[tid] = mx;
    __syncthreads();
    for (int o = 128; o > 0; o >>= 1) {
        if (tid < o) sm[tid] = fmaxf(sm[tid], sm[tid + o]);
        __syncthreads();
    }
    mx = sm[0];
    __syncthreads();
    float sum = 0.0f;
#pragma unroll
    for (int i = 0; i < 8; i++) {
        v[i] = __expf(v[i] - mx);
        sum += v[i];
    }
    sm[tid] = sum;
    __syncthreads();
    for (int o = 128; o > 0; o >>= 1) {
        if (tid < o) sm[tid] += sm[tid + o];
        __syncthreads();
    }
    const float inv = 1.0f / sm[0];
#pragma unroll
    for (int i = 0; i < 8; i++) {
        __nv_bfloat16 h, l;
        split2(v[i] * inv, h, l);
        oh[tid + i * 256] = h;
        ol[tid + i * 256] = l;
    }
}

// ---------------------------------------------------------------------------
// Launcher
// ---------------------------------------------------------------------------
static void* sym(const void* s) {
    void* p = nullptr;
    cudaGetSymbolAddress(&p, s);
    return p;
}

extern "C" void kernel_launch(void* const* d_in, const int* in_sizes, int n_in,
                              void* d_out, int out_size) {
    (void)in_sizes; (void)n_in; (void)out_size;

    const float* query = (const float*)d_in[0];
    const float* key   = (const float*)d_in[1];
    const float* value = (const float*)d_in[2];
    const void*  mask  = d_in[3];
    const float* Wq = (const float*)d_in[4];
    const float* bq = (const float*)d_in[5];
    const float* Wk = (const float*)d_in[6];
    const float* bk = (const float*)d_in[7];
    const float* Wv = (const float*)d_in[8];
    const float* bv = (const float*)d_in[9];
    const float* Wo = (const float*)d_in[10];
    const float* bo = (const float*)d_in[11];
    float* out = (float*)d_out;

    typedef __nv_bfloat16 bf;
    bf* xh0 = (bf*)sym(g_xh);                       bf* xl0 = (bf*)sym(g_xl);
    bf* xh1 = xh0 + (size_t)BATCH * S_LEN * DIM;    bf* xl1 = xl0 + (size_t)BATCH * S_LEN * DIM;
    bf* xh2 = xh1 + (size_t)BATCH * S_LEN * DIM;    bf* xl2 = xl1 + (size_t)BATCH * S_LEN * DIM;
    bf* wth0 = (bf*)sym(g_wth);                     bf* wtl0 = (bf*)sym(g_wtl);
    bf* wth1 = wth0 + (size_t)NHEAD * EDIM * DIM;   bf* wtl1 = wtl0 + (size_t)NHEAD * EDIM * DIM;
    bf* wth2 = wth1 + (size_t)NHEAD * EDIM * DIM;   bf* wtl2 = wtl1 + (size_t)NHEAD * EDIM * DIM;
    bf* woth = (bf*)sym(g_woth);  bf* wotl = (bf*)sym(g_wotl);
    bf* qh = (bf*)sym(g_qh);      bf* ql = (bf*)sym(g_ql);
    bf* kh = (bf*)sym(g_kh);      bf* kl = (bf*)sym(g_kl);
    bf* vth = (bf*)sym(g_vth);    bf* vtl = (bf*)sym(g_vtl);
    float* attn = (float*)sym(g_attn);
    bf* ah = (bf*)sym(g_ah);      bf* al = (bf*)sym(g_al);
    bf* cath = (bf*)sym(g_cath);  bf* catl = (bf*)sym(g_catl);

    cudaFuncSetAttribute(mm_hmma<0>, cudaFuncAttributeMaxDynamicSharedMemorySize, SMEM_DYN);
    cudaFuncSetAttribute(mm_hmma<1>, cudaFuncAttributeMaxDynamicSharedMemorySize, SMEM_DYN);
    cudaFuncSetAttribute(mm_hmma<2>, cudaFuncAttributeMaxDynamicSharedMemorySize, SMEM_DYN);

    const int BIG = 1 << 30;

    detect_mask_kind<<<1, 1>>>(mask);

    // --- input / weight split(+transpose) prep ---
    const int nX = BATCH * S_LEN * DIM;
    split_flat<<<(nX + 255) / 256, 256>>>(query, xh0, xl0, nX);
    split_flat<<<(nX + 255) / 256, 256>>>(key,   xh1, xl1, nX);
    split_flat<<<(nX + 255) / 256, 256>>>(value, xh2, xl2, nX);
    {
        dim3 g(EDIM / 32, DIM / 32, NHEAD), bdim(32, 8);
        split_T<<<g, bdim>>>(Wq, wth0, wtl0, DIM, EDIM);
        split_T<<<g, bdim>>>(Wk, wth1, wtl1, DIM, EDIM);
        split_T<<<g, bdim>>>(Wv, wth2, wtl2, DIM, EDIM);
    }
    {
        dim3 g(EDIM / 32, HE_DIM / 32, 1), bdim(32, 8);
        split_T<<<g, bdim>>>(Wo, woth, wotl, HE_DIM, EDIM);
    }

    // --- projections: X[s,d] @ W^T[e,d]^T -> [b,h,s,e] (v transposed) ---
    {
        dim3 grid(EDIM / TN, S_LEN / TM, BATCH * NHEAD);
        mm_hmma<1><<<grid, 256, SMEM_DYN>>>(
            xh0, xl0, (long)S_LEN * DIM, NHEAD, DIM,
            wth0, wtl0, (long)EDIM * DIM, NHEAD, DIM,
            bq, 1, qh, ql, (long)S_LEN * EDIM, 0, EDIM, DIM);
        mm_hmma<1><<<grid, 256, SMEM_DYN>>>(
            xh1, xl1, (long)S_LEN * DIM, NHEAD, DIM,
            wth1, wtl1, (long)EDIM * DIM, NHEAD, DIM,
            bk, 1, kh, kl, (long)S_LEN * EDIM, 0, EDIM, DIM);
        mm_hmma<2><<<grid, 256, SMEM_DYN>>>(
            xh2, xl2, (long)S_LEN * DIM, NHEAD, DIM,
            wth2, wtl2, (long)EDIM * DIM, NHEAD, DIM,
            bv, 1, vth, vtl, (long)EDIM * S_LEN, 0, S_LEN, DIM);
    }

    // --- scores: q[s,e] @ k[t,e]^T -> fp32 attn ---
    {
        dim3 grid(S_LEN / TN, S_LEN / TM, BATCH * NHEAD);
        mm_hmma<0><<<grid, 256, SMEM_DYN>>>(
            qh, ql, (long)S_LEN * EDIM, 1, EDIM,
            kh, kl, (long)S_LEN * EDIM, BIG, EDIM,
            nullptr, 0, attn, nullptr, (long)S_LEN * S_LEN, 0, S_LEN, EDIM);
    }

    // --- masked softmax -> split bf16 ---
    masked_softmax_split<<<BATCH * NHEAD * S_LEN, 256>>>(mask);

    // --- PV: attn[s,t] @ vT[e,t]^T -> cat[b,s,h*E+e] ---
    {
        dim3 grid(EDIM / TN, S_LEN / TM, BATCH * NHEAD);
        mm_hmma<1><<<grid, 256, SMEM_DYN>>>(
            ah, al, (long)S_LEN * S_LEN, 1, S_LEN,
            vth, vtl, (long)EDIM * S_LEN, BIG, S_LEN,
            nullptr, 0, cath, catl, 0L, 1, HE_DIM, S_LEN);
    }

    // --- output projection: cat[s,he] @ WoT[e,he]^T + bo -> out fp32 ---
    {
        dim3 grid(EDIM / TN, (BATCH * S_LEN) / TM, 1);
        mm_hmma<0><<<grid, 256, SMEM_DYN>>>(
            cath, catl, 0L, 1, HE_DIM,
            woth, wotl, 0L, 1, HE_DIM,
            bo, 2, out, nullptr, 0L, 0, EDIM, HE_DIM);
    }
}

// round 8
// speedup vs baseline: 2.4473x; 1.0028x over previous
#include <cuda_runtime.h>
#include <cuda_bf16.h>
#include <cstdint>
#include <cstddef>

// Problem constants
#define S_LEN   2048
#define BATCH   2
#define DIM     512
#define NHEAD   8
#define EDIM    512
#define HE_DIM  (NHEAD * EDIM)

// GEMM tile config
#define TM 128
#define TN 128
#define KC 64                         // bf16 elems per k-chunk (128B rows, SW128)
#define TILEB (TM * KC * 2)           // 16384 bytes per operand tile
#define STAGE (4 * TILEB)             // Ah, Al, Bh, Bl = 65536
#define NSTAGE 3
#define SMEM_DYN (NSTAGE * STAGE)     // 196608 (epilogue reuses this area)

// ---------------------------------------------------------------------------
// Scratch (device globals — no allocation allowed)
// ---------------------------------------------------------------------------
__device__ __align__(16) __nv_bfloat16 g_xh[3][BATCH * S_LEN * DIM];
__device__ __align__(16) __nv_bfloat16 g_xl[3][BATCH * S_LEN * DIM];
__device__ __align__(16) __nv_bfloat16 g_wth[3][NHEAD * EDIM * DIM];  // W^T per head
__device__ __align__(16) __nv_bfloat16 g_wtl[3][NHEAD * EDIM * DIM];
__device__ __align__(16) __nv_bfloat16 g_woth[EDIM * HE_DIM];
__device__ __align__(16) __nv_bfloat16 g_wotl[EDIM * HE_DIM];
__device__ __align__(16) __nv_bfloat16 g_qh[BATCH * NHEAD * S_LEN * EDIM];
__device__ __align__(16) __nv_bfloat16 g_ql[BATCH * NHEAD * S_LEN * EDIM];
__device__ __align__(16) __nv_bfloat16 g_kh[BATCH * NHEAD * S_LEN * EDIM];
__device__ __align__(16) __nv_bfloat16 g_kl[BATCH * NHEAD * S_LEN * EDIM];
__device__ __align__(16) __nv_bfloat16 g_vth[BATCH * NHEAD * EDIM * S_LEN]; // v^T [e,s]
__device__ __align__(16) __nv_bfloat16 g_vtl[BATCH * NHEAD * EDIM * S_LEN];
__device__ __align__(16) float g_attn[(size_t)BATCH * NHEAD * S_LEN * S_LEN];
__device__ __align__(16) __nv_bfloat16 g_ah[(size_t)BATCH * NHEAD * S_LEN * S_LEN];
__device__ __align__(16) __nv_bfloat16 g_al[(size_t)BATCH * NHEAD * S_LEN * S_LEN];
__device__ __align__(16) __nv_bfloat16 g_cath[BATCH * S_LEN * HE_DIM];
__device__ __align__(16) __nv_bfloat16 g_catl[BATCH * S_LEN * HE_DIM];
__device__ int g_mask_kind;

// ---------------------------------------------------------------------------
// PTX helpers (base sm_103 ISA only: cp.async, ldmatrix, mma.sync)
// ---------------------------------------------------------------------------
__device__ __forceinline__ uint32_t smem_u32(const void* p) {
    uint32_t a;
    asm("{ .reg .u64 t; cvta.to.shared.u64 t, %1; cvt.u32.u64 %0, t; }" : "=r"(a) : "l"(p));
    return a;
}
#define SW128(off) ((off) ^ (((off) >> 3) & 0x70))

#define CP16(sa, gp) asm volatile( \
    "cp.async.cg.shared.global [%0], [%1], 16;" :: "r"(sa), "l"(gp) : "memory")
#define CP_COMMIT() asm volatile("cp.async.commit_group;" ::: "memory")
#define CP_WAIT1() asm volatile("cp.async.wait_group 1;" ::: "memory")
#define CP_WAIT0() asm volatile("cp.async.wait_group 0;" ::: "memory")

#define LDSM4(r, a) asm volatile( \
    "ldmatrix.sync.aligned.m8n8.x4.shared.b16 {%0,%1,%2,%3}, [%4];" \
    : "=r"((r)[0]), "=r"((r)[1]), "=r"((r)[2]), "=r"((r)[3]) : "r"(a))

#define MMA16816(d, a, b0, b1) asm volatile( \
    "mma.sync.aligned.m16n8k16.row.col.f32.bf16.bf16.f32 " \
    "{%0,%1,%2,%3}, {%4,%5,%6,%7}, {%8,%9}, {%0,%1,%2,%3};" \
    : "+f"((d)[0]), "+f"((d)[1]), "+f"((d)[2]), "+f"((d)[3]) \
    : "r"((a)[0]), "r"((a)[1]), "r"((a)[2]), "r"((a)[3]), "r"(b0), "r"(b1))

__device__ __forceinline__ void split2(float v, __nv_bfloat16& h, __nv_bfloat16& l) {
    h = __float2bfloat16(v);
    l = __float2bfloat16(v - __bfloat162float(h));
}

// ---------------------------------------------------------------------------
// Mask dtype detection (bool may arrive as u8 / i32 / f32)
// ---------------------------------------------------------------------------
__global__ void detect_mask_kind(const void* __restrict__ mask) {
    const unsigned int* w = (const unsigned int*)mask;
    bool all01 = true, allf = true;
    for (int i = 0; i < 256; i++) {
        unsigned int x = w[i];
        if (x > 1u) all01 = false;
        if (x != 0u && x != 0x3F800000u) allf = false;
    }
    g_mask_kind = all01 ? 1 : (allf ? 2 : 0);
}

// ---------------------------------------------------------------------------
// Split fp32 -> (hi, lo) bf16, flat
// ---------------------------------------------------------------------------
__global__ void split_flat(const float* __restrict__ src,
                           __nv_bfloat16* __restrict__ hi,
                           __nv_bfloat16* __restrict__ lo, int n) {
    int i = blockIdx.x * blockDim.x + threadIdx.x;
    if (i < n) {
        __nv_bfloat16 h, l;
        split2(src[i], h, l);
        hi[i] = h;
        lo[i] = l;
    }
}

// ---------------------------------------------------------------------------
// Split + transpose: src [Z][R][C] fp32 -> dst [Z][C][R] bf16 hi/lo
// ---------------------------------------------------------------------------
__global__ void split_T(const float* __restrict__ src,
                        __nv_bfloat16* __restrict__ hi,
                        __nv_bfloat16* __restrict__ lo, int R, int C) {
    __shared__ float tile[32][33];
    const int z = blockIdx.z;
    const float* s = src + (size_t)z * R * C;
    __nv_bfloat16* dh = hi + (size_t)z * R * C;
    __nv_bfloat16* dl = lo + (size_t)z * R * C;
    const int c0 = blockIdx.x * 32, r0 = blockIdx.y * 32;
    const int tx = threadIdx.x, ty = threadIdx.y;
#pragma unroll
    for (int i = 0; i < 4; i++)
        tile[ty + i * 8][tx] = s[(size_t)(r0 + ty + i * 8) * C + c0 + tx];
    __syncthreads();
#pragma unroll
    for (int i = 0; i < 4; i++) {
        __nv_bfloat16 h, l;
        split2(tile[tx][ty + i * 8], h, l);
        const size_t idx = (size_t)(c0 + ty + i * 8) * R + r0 + tx;
        dh[idx] = h;
        dl[idx] = l;
    }
}

// ---------------------------------------------------------------------------
// bf16x3 HMMA GEMM: C = A @ B^T (+bias). Both operands K-major as (hi,lo).
// 128x128 tile / CTA, K-chunk 64, 3-stage cp.async pipeline, mma.sync.
// 8 warps: warpM = wid&1 (64 rows), warpN = wid>>1 (32 cols).
// OM: 0 = fp32 out, 1 = split-bf16 out, 2 = split-bf16 transposed out.
// ---------------------------------------------------------------------------
template <int OM>
__global__ __launch_bounds__(256, 1)
void mm_hmma(const __nv_bfloat16* __restrict__ Ah, const __nv_bfloat16* __restrict__ Al,
             long aBatch, int aDiv, int lda,
             const __nv_bfloat16* __restrict__ Bh, const __nv_bfloat16* __restrict__ Bl,
             long bBatch, int bMod, int ldb,
             const float* __restrict__ biasAll, int biasMode,
             void* __restrict__ C0, __nv_bfloat16* __restrict__ Cl,
             long cBatch, int cMode, int ldc, int K) {
    extern __shared__ char smem[];
    const uint32_t sb = smem_u32(smem);
    const int t = threadIdx.x;
    const int lane = t & 31;
    const int wid = t >> 5;
    const int warpM = wid & 1;
    const int warpN = wid >> 1;
    const int z = blockIdx.z;
    const int row0 = blockIdx.y * TM;
    const int col0 = blockIdx.x * TN;

    const __nv_bfloat16* pAh = Ah + (size_t)(z / aDiv) * (size_t)aBatch;
    const __nv_bfloat16* pAl = Al + (size_t)(z / aDiv) * (size_t)aBatch;
    const __nv_bfloat16* pBh = Bh + (size_t)(z % bMod) * (size_t)bBatch;
    const __nv_bfloat16* pBl = Bl + (size_t)(z % bMod) * (size_t)bBatch;

    float acc[4][4][4] = {};

    auto issue = [&](int c) {
        const int k0 = c * KC;
        const uint32_t s0 = sb + (c % NSTAGE) * STAGE;
#pragma unroll
        for (int i = 0; i < 4; i++) {
            const int ch = t + i * 256;           // 1024 16B chunks per tile
            const int r = ch >> 3;                // 0..127
            const int q = (ch & 7) * 8;           // bf16 col
            const uint32_t so = SW128((uint32_t)(r * 128 + q * 2));
            const size_t ao = (size_t)(row0 + r) * lda + k0 + q;
            const size_t bo = (size_t)(col0 + r) * ldb + k0 + q;
            CP16(s0 + so, pAh + ao);
            CP16(s0 + TILEB + so, pAl + ao);
            CP16(s0 + 2 * TILEB + so, pBh + bo);
            CP16(s0 + 3 * TILEB + so, pBl + bo);
        }
    };

    const int arow = lane & 15;
    const int koff = (lane >> 4) * 16;            // byte offset of k half

    auto compute = [&](int c) {
        const uint32_t s0 = sb + (c % NSTAGE) * STAGE;
#pragma unroll
        for (int ks = 0; ks < 4; ks++) {
            uint32_t fah[4][4], fal[4][4], fbh[2][4], fbl[2][4];
#pragma unroll
            for (int mt = 0; mt < 4; mt++) {
                const uint32_t off = SW128(
                    (uint32_t)((warpM * 64 + mt * 16 + arow) * 128 + ks * 32 + koff));
                LDSM4(fah[mt], s0 + off);
                LDSM4(fal[mt], s0 + TILEB + off);
            }
#pragma unroll
            for (int p = 0; p < 2; p++) {
                const uint32_t off = SW128(
                    (uint32_t)((warpN * 32 + p * 16 + arow) * 128 + ks * 32 + koff));
                LDSM4(fbh[p], s0 + 2 * TILEB + off);
                LDSM4(fbl[p], s0 + 3 * TILEB + off);
            }
#pragma unroll
            for (int mt = 0; mt < 4; mt++)
#pragma unroll
                for (int nt = 0; nt < 4; nt++) {
                    const int p = nt >> 1, o = nt & 1;
                    MMA16816(acc[mt][nt], fah[mt], fbh[p][o], fbh[p][o + 2]);
                    MMA16816(acc[mt][nt], fah[mt], fbl[p][o], fbl[p][o + 2]);
                    MMA16816(acc[mt][nt], fal[mt], fbh[p][o], fbh[p][o + 2]);
                }
        }
    };

    const int NC = K / KC;
    issue(0);
    CP_COMMIT();
    if (NC > 1) {
        issue(1);
        CP_COMMIT();
    }
    for (int c = 0; c < NC; c++) {
        if (c + 1 < NC) CP_WAIT1(); else CP_WAIT0();
        __syncthreads();                  // chunk c visible to all warps;
                                          // also fences compute(c-1) before
                                          // any warp issues into (c+1)%NSTAGE... (c+2 below)
        compute(c);
        if (c + 2 < NC) {
            issue(c + 2);                 // buffer (c+2)%NSTAGE == (c-1)%NSTAGE,
            CP_COMMIT();                  // consumed at compute(c-1), fenced above
        }
    }
    __syncthreads();                      // all compute done before smem reuse

    // ---------------- Epilogue: accum -> smem -> global ----------------
    float* esm = (float*)smem;                    // [128][132]
#pragma unroll
    for (int mt = 0; mt < 4; mt++)
#pragma unroll
        for (int nt = 0; nt < 4; nt++) {
            const int r = warpM * 64 + mt * 16 + (lane >> 2);
            const int cc = warpN * 32 + nt * 8 + (lane & 3) * 2;
            *(float2*)&esm[r * 132 + cc] = make_float2(acc[mt][nt][0], acc[mt][nt][1]);
            *(float2*)&esm[(r + 8) * 132 + cc] = make_float2(acc[mt][nt][2], acc[mt][nt][3]);
        }
    __syncthreads();

    size_t zoff;
    if (cMode == 0) zoff = (size_t)z * (size_t)cBatch;
    else zoff = (size_t)(z / NHEAD) * S_LEN * HE_DIM + (size_t)(z % NHEAD) * EDIM;
    const float* bias = nullptr;
    if (biasMode == 1) bias = biasAll + (size_t)(z % NHEAD) * EDIM;
    else if (biasMode == 2) bias = biasAll;

    if (OM != 2) {
        const int m = t >> 1, cs = (t & 1) * 64;
#pragma unroll
        for (int jj = 0; jj < 64; jj += 16) {
            float v[16];
#pragma unroll
            for (int j = 0; j < 16; j++) {
                v[j] = esm[m * 132 + cs + jj + j];
                if (biasMode) v[j] += bias[col0 + cs + jj + j];
            }
            const size_t idx = zoff + (size_t)(row0 + m) * ldc + col0 + cs + jj;
            if (OM == 0) {
                float4* dst = (float4*)((float*)C0 + idx);
#pragma unroll
                for (int j = 0; j < 4; j++)
                    dst[j] = make_float4(v[4 * j], v[4 * j + 1], v[4 * j + 2], v[4 * j + 3]);
            } else {
                __align__(16) __nv_bfloat16 hb[16], lb[16];
#pragma unroll
                for (int j = 0; j < 16; j++) split2(v[j], hb[j], lb[j]);
                *(uint4*)((__nv_bfloat16*)C0 + idx) = *(uint4*)hb;
                *(uint4*)((__nv_bfloat16*)C0 + idx + 8) = *(uint4*)(hb + 8);
                *(uint4*)(Cl + idx) = *(uint4*)lb;
                *(uint4*)(Cl + idx + 8) = *(uint4*)(lb + 8);
            }
        }
    } else {
        const int e = t >> 1, m0 = (t & 1) * 64;
        const float bv = biasMode ? bias[col0 + e] : 0.0f;
#pragma unroll
        for (int jj = 0; jj < 64; jj += 16) {
            __align__(16) __nv_bfloat16 hb[16], lb[16];
#pragma unroll
            for (int j = 0; j < 16; j++)
                split2(esm[(m0 + jj + j) * 132 + e] + bv, hb[j], lb[j]);
            const size_t idx = zoff + (size_t)(col0 + e) * ldc + row0 + m0 + jj;
            *(uint4*)((__nv_bfloat16*)C0 + idx) = *(uint4*)hb;
            *(uint4*)((__nv_bfloat16*)C0 + idx + 8) = *(uint4*)(hb + 8);
            *(uint4*)(Cl + idx) = *(uint4*)lb;
            *(uint4*)(Cl + idx + 8) = *(uint4*)(lb + 8);
        }
    }
}

// ---------------------------------------------------------------------------
// Masked softmax: reads fp32 g_attn row, writes split bf16 to g_ah/g_al.
// ---------------------------------------------------------------------------
__global__ void masked_softmax_split(const void* __restrict__ mask) {
    const int z = blockIdx.x;
    const int b = z / (NHEAD * S_LEN);
    const int s = z % S_LEN;
    const float* row = g_attn + (size_t)z * S_LEN;
    __nv_bfloat16* oh = g_ah + (size_t)z * S_LEN;
    __nv_bfloat16* ol = g_al + (size_t)z * S_LEN;
    const size_t mbase = (size_t)b * S_LEN * S_LEN + (size_t)s * S_LEN;
    const int kind = g_mask_kind;
    const int tid = threadIdx.x;

    float v[8];
    float mx = -3.0e38f;
#pragma unroll
    for (int i = 0; i < 8; i++) {
        const int tt = tid + i * 256;
        bool mk;
        if (kind == 1)      mk = ((const int*)mask)[mbase + tt] != 0;
        else if (kind == 2) mk = ((const float*)mask)[mbase + tt] != 0.0f;
        else                mk = ((const unsigned char*)mask)[mbase + tt] != 0;
        const float x = mk ? row[tt] : -1.0e9f;
        v[i] = x;
        mx = fmaxf(mx, x);
    }
    __shared__ float sm[256];
    sm[tid] = mx;
    __syncthreads();
    for (int o = 128; o > 0; o >>= 1) {
        if (tid < o) sm[tid] = fmaxf(sm[tid], sm[tid + o]);
        __syncthreads();
    }
    mx = sm[0];
    __syncthreads();
    float sum = 0.0f;
#pragma unroll
    for (int i = 0; i < 8; i++) {
        v[i] = __expf(v[i] - mx);
        sum += v[i];
    }
    sm[tid] = sum;
    __syncthreads();
    for (int o = 128; o > 0; o >>= 1) {
        if (tid < o) sm[tid] += sm[tid + o];
        __syncthreads();
    }
    const float inv = 1.0f / sm[0];
#pragma unroll
    for (int i = 0; i < 8; i++) {
        __nv_bfloat16 h, l;
        split2(v[i] * inv, h, l);
        oh[tid + i * 256] = h;
        ol[tid + i * 256] = l;
    }
}

// ---------------------------------------------------------------------------
// Launcher
// ---------------------------------------------------------------------------
static void* sym(const void* s) {
    void* p = nullptr;
    cudaGetSymbolAddress(&p, s);
    return p;
}

extern "C" void kernel_launch(void* const* d_in, const int* in_sizes, int n_in,
                              void* d_out, int out_size) {
    (void)in_sizes; (void)n_in; (void)out_size;

    const float* query = (const float*)d_in[0];
    const float* key   = (const float*)d_in[1];
    const float* value = (const float*)d_in[2];
    const void*  mask  = d_in[3];
    const float* Wq = (const float*)d_in[4];
    const float* bq = (const float*)d_in[5];
    const float* Wk = (const float*)d_in[6];
    const float* bk = (const float*)d_in[7];
    const float* Wv = (const float*)d_in[8];
    const float* bv = (const float*)d_in[9];
    const float* Wo = (const float*)d_in[10];
    const float* bo = (const float*)d_in[11];
    float* out = (float*)d_out;

    typedef __nv_bfloat16 bf;
    bf* xh0 = (bf*)sym(g_xh);                       bf* xl0 = (bf*)sym(g_xl);
    bf* xh1 = xh0 + (size_t)BATCH * S_LEN * DIM;    bf* xl1 = xl0 + (size_t)BATCH * S_LEN * DIM;
    bf* xh2 = xh1 + (size_t)BATCH * S_LEN * DIM;    bf* xl2 = xl1 + (size_t)BATCH * S_LEN * DIM;
    bf* wth0 = (bf*)sym(g_wth);                     bf* wtl0 = (bf*)sym(g_wtl);
    bf* wth1 = wth0 + (size_t)NHEAD * EDIM * DIM;   bf* wtl1 = wtl0 + (size_t)NHEAD * EDIM * DIM;
    bf* wth2 = wth1 + (size_t)NHEAD * EDIM * DIM;   bf* wtl2 = wtl1 + (size_t)NHEAD * EDIM * DIM;
    bf* woth = (bf*)sym(g_woth);  bf* wotl = (bf*)sym(g_wotl);
    bf* qh = (bf*)sym(g_qh);      bf* ql = (bf*)sym(g_ql);
    bf* kh = (bf*)sym(g_kh);      bf* kl = (bf*)sym(g_kl);
    bf* vth = (bf*)sym(g_vth);    bf* vtl = (bf*)sym(g_vtl);
    float* attn = (float*)sym(g_attn);
    bf* ah = (bf*)sym(g_ah);      bf* al = (bf*)sym(g_al);
    bf* cath = (bf*)sym(g_cath);  bf* catl = (bf*)sym(g_catl);

    cudaFuncSetAttribute(mm_hmma<0>, cudaFuncAttributeMaxDynamicSharedMemorySize, SMEM_DYN);
    cudaFuncSetAttribute(mm_hmma<1>, cudaFuncAttributeMaxDynamicSharedMemorySize, SMEM_DYN);
    cudaFuncSetAttribute(mm_hmma<2>, cudaFuncAttributeMaxDynamicSharedMemorySize, SMEM_DYN);

    const int BIG = 1 << 30;

    detect_mask_kind<<<1, 1>>>(mask);

    // --- input / weight split(+transpose) prep ---
    const int nX = BATCH * S_LEN * DIM;
    split_flat<<<(nX + 255) / 256, 256>>>(query, xh0, xl0, nX);
    split_flat<<<(nX + 255) / 256, 256>>>(key,   xh1, xl1, nX);
    split_flat<<<(nX + 255) / 256, 256>>>(value, xh2, xl2, nX);
    {
        dim3 g(EDIM / 32, DIM / 32, NHEAD), bdim(32, 8);
        split_T<<<g, bdim>>>(Wq, wth0, wtl0, DIM, EDIM);
        split_T<<<g, bdim>>>(Wk, wth1, wtl1, DIM, EDIM);
        split_T<<<g, bdim>>>(Wv, wth2, wtl2, DIM, EDIM);
    }
    {
        dim3 g(EDIM / 32, HE_DIM / 32, 1), bdim(32, 8);
        split_T<<<g, bdim>>>(Wo, woth, wotl, HE_DIM, EDIM);
    }

    // --- projections: X[s,d] @ W^T[e,d]^T -> [b,h,s,e] (v transposed) ---
    {
        dim3 grid(EDIM / TN, S_LEN / TM, BATCH * NHEAD);
        mm_hmma<1><<<grid, 256, SMEM_DYN>>>(
            xh0, xl0, (long)S_LEN * DIM, NHEAD, DIM,
            wth0, wtl0, (long)EDIM * DIM, NHEAD, DIM,
            bq, 1, qh, ql, (long)S_LEN * EDIM, 0, EDIM, DIM);
        mm_hmma<1><<<grid, 256, SMEM_DYN>>>(
            xh1, xl1, (long)S_LEN * DIM, NHEAD, DIM,
            wth1, wtl1, (long)EDIM * DIM, NHEAD, DIM,
            bk, 1, kh, kl, (long)S_LEN * EDIM, 0, EDIM, DIM);
        mm_hmma<2><<<grid, 256, SMEM_DYN>>>(
            xh2, xl2, (long)S_LEN * DIM, NHEAD, DIM,
            wth2, wtl2, (long)EDIM * DIM, NHEAD, DIM,
            bv, 1, vth, vtl, (long)EDIM * S_LEN, 0, S_LEN, DIM);
    }

    // --- scores: q[s,e] @ k[t,e]^T -> fp32 attn ---
    {
        dim3 grid(S_LEN / TN, S_LEN / TM, BATCH * NHEAD);
        mm_hmma<0><<<grid, 256, SMEM_DYN>>>(
            qh, ql, (long)S_LEN * EDIM, 1, EDIM,
            kh, kl, (long)S_LEN * EDIM, BIG, EDIM,
            nullptr, 0, attn, nullptr, (long)S_LEN * S_LEN, 0, S_LEN, EDIM);
    }

    // --- masked softmax -> split bf16 ---
    masked_softmax_split<<<BATCH * NHEAD * S_LEN, 256>>>(mask);

    // --- PV: attn[s,t] @ vT[e,t]^T -> cat[b,s,h*E+e] ---
    {
        dim3 grid(EDIM / TN, S_LEN / TM, BATCH * NHEAD);
        mm_hmma<1><<<grid, 256, SMEM_DYN>>>(
            ah, al, (long)S_LEN * S_LEN, 1, S_LEN,
            vth, vtl, (long)EDIM * S_LEN, BIG, S_LEN,
            nullptr, 0, cath, catl, 0L, 1, HE_DIM, S_LEN);
    }

    // --- output projection: cat[s,he] @ WoT[e,he]^T + bo -> out fp32 ---
    {
        dim3 grid(EDIM / TN, (BATCH * S_LEN) / 128, 1);
        mm_hmma<0><<<grid, 256, SMEM_DYN>>>(
            cath, catl, 0L, 1, HE_DIM,
            woth, wotl, 0L, 1, HE_DIM,
            bo, 2, out, nullptr, 0L, 0, EDIM, HE_DIM);
    }
}

// round 9
// speedup vs baseline: 2.5790x; 1.0538x over previous
#include <cuda_runtime.h>
#include <cuda_bf16.h>
#include <cstdint>
#include <cstddef>

// Problem constants
#define S_LEN   2048
#define BATCH   2
#define DIM     512
#define NHEAD   8
#define EDIM    512
#define HE_DIM  (NHEAD * EDIM)

// GEMM tile config
#define TM 128
#define TN 128
#define KC 32                         // bf16 elems per k-chunk (64B rows, SW64)
#define TILEB (TM * KC * 2)           // 8192 bytes per operand tile
#define STAGE (4 * TILEB)             // Ah, Al, Bh, Bl = 32768
#define NSTAGE 3
#define SMEM_DYN (NSTAGE * STAGE)     // 98304 -> 2 CTAs per SM

// ---------------------------------------------------------------------------
// Scratch (device globals — no allocation allowed)
// ---------------------------------------------------------------------------
__device__ __align__(16) __nv_bfloat16 g_xh[3][BATCH * S_LEN * DIM];
__device__ __align__(16) __nv_bfloat16 g_xl[3][BATCH * S_LEN * DIM];
__device__ __align__(16) __nv_bfloat16 g_wth[3][NHEAD * EDIM * DIM];  // W^T per head
__device__ __align__(16) __nv_bfloat16 g_wtl[3][NHEAD * EDIM * DIM];
__device__ __align__(16) __nv_bfloat16 g_woth[EDIM * HE_DIM];
__device__ __align__(16) __nv_bfloat16 g_wotl[EDIM * HE_DIM];
__device__ __align__(16) __nv_bfloat16 g_qh[BATCH * NHEAD * S_LEN * EDIM];
__device__ __align__(16) __nv_bfloat16 g_ql[BATCH * NHEAD * S_LEN * EDIM];
__device__ __align__(16) __nv_bfloat16 g_kh[BATCH * NHEAD * S_LEN * EDIM];
__device__ __align__(16) __nv_bfloat16 g_kl[BATCH * NHEAD * S_LEN * EDIM];
__device__ __align__(16) __nv_bfloat16 g_vth[BATCH * NHEAD * EDIM * S_LEN]; // v^T [e,s]
__device__ __align__(16) __nv_bfloat16 g_vtl[BATCH * NHEAD * EDIM * S_LEN];
__device__ __align__(16) float g_attn[(size_t)BATCH * NHEAD * S_LEN * S_LEN];
__device__ __align__(16) __nv_bfloat16 g_ah[(size_t)BATCH * NHEAD * S_LEN * S_LEN];
__device__ __align__(16) __nv_bfloat16 g_al[(size_t)BATCH * NHEAD * S_LEN * S_LEN];
__device__ __align__(16) __nv_bfloat16 g_cath[BATCH * S_LEN * HE_DIM];
__device__ __align__(16) __nv_bfloat16 g_catl[BATCH * S_LEN * HE_DIM];
__device__ int g_mask_kind;

// ---------------------------------------------------------------------------
// PTX helpers (base sm_103 ISA only: cp.async, ldmatrix, mma.sync)
// ---------------------------------------------------------------------------
__device__ __forceinline__ uint32_t smem_u32(const void* p) {
    uint32_t a;
    asm("{ .reg .u64 t; cvta.to.shared.u64 t, %1; cvt.u32.u64 %0, t; }" : "=r"(a) : "l"(p));
    return a;
}
// 64B-row swizzle (Swizzle<2,4,3>): XOR bits [4:6) with bits [7:9)
#define SW64(off) ((off) ^ (((off) >> 3) & 0x30))

#define CP16(sa, gp) asm volatile( \
    "cp.async.cg.shared.global [%0], [%1], 16;" :: "r"(sa), "l"(gp) : "memory")
#define CP_COMMIT() asm volatile("cp.async.commit_group;" ::: "memory")
#define CP_WAIT1() asm volatile("cp.async.wait_group 1;" ::: "memory")
#define CP_WAIT0() asm volatile("cp.async.wait_group 0;" ::: "memory")

#define LDSM4(r, a) asm volatile( \
    "ldmatrix.sync.aligned.m8n8.x4.shared.b16 {%0,%1,%2,%3}, [%4];" \
    : "=r"((r)[0]), "=r"((r)[1]), "=r"((r)[2]), "=r"((r)[3]) : "r"(a))

#define MMA16816(d, a, b0, b1) asm volatile( \
    "mma.sync.aligned.m16n8k16.row.col.f32.bf16.bf16.f32 " \
    "{%0,%1,%2,%3}, {%4,%5,%6,%7}, {%8,%9}, {%0,%1,%2,%3};" \
    : "+f"((d)[0]), "+f"((d)[1]), "+f"((d)[2]), "+f"((d)[3]) \
    : "r"((a)[0]), "r"((a)[1]), "r"((a)[2]), "r"((a)[3]), "r"(b0), "r"(b1))

__device__ __forceinline__ void split2(float v, __nv_bfloat16& h, __nv_bfloat16& l) {
    h = __float2bfloat16(v);
    l = __float2bfloat16(v - __bfloat162float(h));
}

// ---------------------------------------------------------------------------
// Mask dtype detection (bool may arrive as u8 / i32 / f32)
// ---------------------------------------------------------------------------
__global__ void detect_mask_kind(const void* __restrict__ mask) {
    const unsigned int* w = (const unsigned int*)mask;
    bool all01 = true, allf = true;
    for (int i = 0; i < 256; i++) {
        unsigned int x = w[i];
        if (x > 1u) all01 = false;
        if (x != 0u && x != 0x3F800000u) allf = false;
    }
    g_mask_kind = all01 ? 1 : (allf ? 2 : 0);
}

// ---------------------------------------------------------------------------
// Split fp32 -> (hi, lo) bf16, flat
// ---------------------------------------------------------------------------
__global__ void split_flat(const float* __restrict__ src,
                           __nv_bfloat16* __restrict__ hi,
                           __nv_bfloat16* __restrict__ lo, int n) {
    int i = blockIdx.x * blockDim.x + threadIdx.x;
    if (i < n) {
        __nv_bfloat16 h, l;
        split2(src[i], h, l);
        hi[i] = h;
        lo[i] = l;
    }
}

// ---------------------------------------------------------------------------
// Split + transpose: src [Z][R][C] fp32 -> dst [Z][C][R] bf16 hi/lo
// ---------------------------------------------------------------------------
__global__ void split_T(const float* __restrict__ src,
                        __nv_bfloat16* __restrict__ hi,
                        __nv_bfloat16* __restrict__ lo, int R, int C) {
    __shared__ float tile[32][33];
    const int z = blockIdx.z;
    const float* s = src + (size_t)z * R * C;
    __nv_bfloat16* dh = hi + (size_t)z * R * C;
    __nv_bfloat16* dl = lo + (size_t)z * R * C;
    const int c0 = blockIdx.x * 32, r0 = blockIdx.y * 32;
    const int tx = threadIdx.x, ty = threadIdx.y;
#pragma unroll
    for (int i = 0; i < 4; i++)
        tile[ty + i * 8][tx] = s[(size_t)(r0 + ty + i * 8) * C + c0 + tx];
    __syncthreads();
#pragma unroll
    for (int i = 0; i < 4; i++) {
        __nv_bfloat16 h, l;
        split2(tile[tx][ty + i * 8], h, l);
        const size_t idx = (size_t)(c0 + ty + i * 8) * R + r0 + tx;
        dh[idx] = h;
        dl[idx] = l;
    }
}

// ---------------------------------------------------------------------------
// bf16x3 HMMA GEMM: C = A @ B^T (+bias). Both operands K-major as (hi,lo).
// 128x128 tile / CTA, K-chunk 32, 3-stage cp.async pipeline, 2 CTAs/SM.
// 8 warps: warpM = wid&1 (64 rows), warpN = wid>>1 (32 cols).
// OM: 0 = fp32 out, 1 = split-bf16 out, 2 = split-bf16 transposed out.
// ---------------------------------------------------------------------------
template <int OM>
__global__ __launch_bounds__(256, 2)
void mm_hmma(const __nv_bfloat16* __restrict__ Ah, const __nv_bfloat16* __restrict__ Al,
             long aBatch, int aDiv, int lda,
             const __nv_bfloat16* __restrict__ Bh, const __nv_bfloat16* __restrict__ Bl,
             long bBatch, int bMod, int ldb,
             const float* __restrict__ biasAll, int biasMode,
             void* __restrict__ C0, __nv_bfloat16* __restrict__ Cl,
             long cBatch, int cMode, int ldc, int K) {
    extern __shared__ char smem[];
    const uint32_t sb = smem_u32(smem);
    const int t = threadIdx.x;
    const int lane = t & 31;
    const int wid = t >> 5;
    const int warpM = wid & 1;
    const int warpN = wid >> 1;
    const int z = blockIdx.z;
    const int row0 = blockIdx.y * TM;
    const int col0 = blockIdx.x * TN;

    const __nv_bfloat16* pAh = Ah + (size_t)(z / aDiv) * (size_t)aBatch;
    const __nv_bfloat16* pAl = Al + (size_t)(z / aDiv) * (size_t)aBatch;
    const __nv_bfloat16* pBh = Bh + (size_t)(z % bMod) * (size_t)bBatch;
    const __nv_bfloat16* pBl = Bl + (size_t)(z % bMod) * (size_t)bBatch;

    float acc[4][4][4] = {};

    auto issue = [&](int c) {
        const int k0 = c * KC;
        const uint32_t s0 = sb + (c % NSTAGE) * STAGE;
#pragma unroll
        for (int i = 0; i < 2; i++) {
            const int ch = t + i * 256;           // 512 16B chunks per tile
            const int r = ch >> 2;                // 0..127
            const int q = (ch & 3) * 8;           // bf16 col
            const uint32_t so = SW64((uint32_t)(r * 64 + q * 2));
            const size_t ao = (size_t)(row0 + r) * lda + k0 + q;
            const size_t bo = (size_t)(col0 + r) * ldb + k0 + q;
            CP16(s0 + so, pAh + ao);
            CP16(s0 + TILEB + so, pAl + ao);
            CP16(s0 + 2 * TILEB + so, pBh + bo);
            CP16(s0 + 3 * TILEB + so, pBl + bo);
        }
    };

    const int arow = lane & 15;
    const int koff = (lane >> 4) * 16;            // byte offset of k half

    auto compute = [&](int c) {
        const uint32_t s0 = sb + (c % NSTAGE) * STAGE;
#pragma unroll
        for (int ks = 0; ks < 2; ks++) {
            // Term order chosen to cap live fragment registers (~40):
            // load Ah,Bh -> hh; load Al -> lh (Bh dies); load Bl -> hl (Al dead)
            uint32_t fah[4][4], fx[4][4], fb[2][4];
#pragma unroll
            for (int mt = 0; mt < 4; mt++) {
                const uint32_t off = SW64(
                    (uint32_t)((warpM * 64 + mt * 16 + arow) * 64 + ks * 32 + koff));
                LDSM4(fah[mt], s0 + off);
            }
#pragma unroll
            for (int p = 0; p < 2; p++) {
                const uint32_t off = SW64(
                    (uint32_t)((warpN * 32 + p * 16 + arow) * 64 + ks * 32 + koff));
                LDSM4(fb[p], s0 + 2 * TILEB + off);
            }
#pragma unroll
            for (int mt = 0; mt < 4; mt++)
#pragma unroll
                for (int nt = 0; nt < 4; nt++) {
                    const int p = nt >> 1, o = nt & 1;
                    MMA16816(acc[mt][nt], fah[mt], fb[p][o], fb[p][o + 2]);
                }
#pragma unroll
            for (int mt = 0; mt < 4; mt++) {
                const uint32_t off = SW64(
                    (uint32_t)((warpM * 64 + mt * 16 + arow) * 64 + ks * 32 + koff));
                LDSM4(fx[mt], s0 + TILEB + off);   // Al
            }
#pragma unroll
            for (int mt = 0; mt < 4; mt++)
#pragma unroll
                for (int nt = 0; nt < 4; nt++) {
                    const int p = nt >> 1, o = nt & 1;
                    MMA16816(acc[mt][nt], fx[mt], fb[p][o], fb[p][o + 2]);
                }
#pragma unroll
            for (int p = 0; p < 2; p++) {
                const uint32_t off = SW64(
                    (uint32_t)((warpN * 32 + p * 16 + arow) * 64 + ks * 32 + koff));
                LDSM4(fb[p], s0 + 3 * TILEB + off);  // Bl (reuse fb regs)
            }
#pragma unroll
            for (int mt = 0; mt < 4; mt++)
#pragma unroll
                for (int nt = 0; nt < 4; nt++) {
                    const int p = nt >> 1, o = nt & 1;
                    MMA16816(acc[mt][nt], fah[mt], fb[p][o], fb[p][o + 2]);
                }
        }
    };

    const int NC = K / KC;
    issue(0);
    CP_COMMIT();
    issue(1);
    CP_COMMIT();
    for (int c = 0; c < NC; c++) {
        if (c + 1 < NC) CP_WAIT1(); else CP_WAIT0();
        __syncthreads();                  // chunk c visible; fences compute(c-1)
                                          // before issue into its buffer below
        compute(c);
        if (c + 2 < NC) {
            issue(c + 2);
            CP_COMMIT();
        }
    }
    __syncthreads();                      // all compute done before smem reuse

    // ---------------- Epilogue: accum -> smem -> global ----------------
    float* esm = (float*)smem;                    // [128][132]
#pragma unroll
    for (int mt = 0; mt < 4; mt++)
#pragma unroll
        for (int nt = 0; nt < 4; nt++) {
            const int r = warpM * 64 + mt * 16 + (lane >> 2);
            const int cc = warpN * 32 + nt * 8 + (lane & 3) * 2;
            *(float2*)&esm[r * 132 + cc] = make_float2(acc[mt][nt][0], acc[mt][nt][1]);
            *(float2*)&esm[(r + 8) * 132 + cc] = make_float2(acc[mt][nt][2], acc[mt][nt][3]);
        }
    __syncthreads();

    size_t zoff;
    if (cMode == 0) zoff = (size_t)z * (size_t)cBatch;
    else zoff = (size_t)(z / NHEAD) * S_LEN * HE_DIM + (size_t)(z % NHEAD) * EDIM;
    const float* bias = nullptr;
    if (biasMode == 1) bias = biasAll + (size_t)(z % NHEAD) * EDIM;
    else if (biasMode == 2) bias = biasAll;

    if (OM != 2) {
        const int m = t >> 1, cs = (t & 1) * 64;
#pragma unroll
        for (int jj = 0; jj < 64; jj += 16) {
            float v[16];
#pragma unroll
            for (int j = 0; j < 16; j++) {
                v[j] = esm[m * 132 + cs + jj + j];
                if (biasMode) v[j] += bias[col0 + cs + jj + j];
            }
            const size_t idx = zoff + (size_t)(row0 + m) * ldc + col0 + cs + jj;
            if (OM == 0) {
                float4* dst = (float4*)((float*)C0 + idx);
#pragma unroll
                for (int j = 0; j < 4; j++)
                    dst[j] = make_float4(v[4 * j], v[4 * j + 1], v[4 * j + 2], v[4 * j + 3]);
            } else {
                __align__(16) __nv_bfloat16 hb[16], lb[16];
#pragma unroll
                for (int j = 0; j < 16; j++) split2(v[j], hb[j], lb[j]);
                *(uint4*)((__nv_bfloat16*)C0 + idx) = *(uint4*)hb;
                *(uint4*)((__nv_bfloat16*)C0 + idx + 8) = *(uint4*)(hb + 8);
                *(uint4*)(Cl + idx) = *(uint4*)lb;
                *(uint4*)(Cl + idx + 8) = *(uint4*)(lb + 8);
            }
        }
    } else {
        const int e = t >> 1, m0 = (t & 1) * 64;
        const float bv = biasMode ? bias[col0 + e] : 0.0f;
#pragma unroll
        for (int jj = 0; jj < 64; jj += 16) {
            __align__(16) __nv_bfloat16 hb[16], lb[16];
#pragma unroll
            for (int j = 0; j < 16; j++)
                split2(esm[(m0 + jj + j) * 132 + e] + bv, hb[j], lb[j]);
            const size_t idx = zoff + (size_t)(col0 + e) * ldc + row0 + m0 + jj;
            *(uint4*)((__nv_bfloat16*)C0 + idx) = *(uint4*)hb;
            *(uint4*)((__nv_bfloat16*)C0 + idx + 8) = *(uint4*)(hb + 8);
            *(uint4*)(Cl + idx) = *(uint4*)lb;
            *(uint4*)(Cl + idx + 8) = *(uint4*)(lb + 8);
        }
    }
}

// ---------------------------------------------------------------------------
// Masked softmax: reads fp32 g_attn row, writes split bf16 to g_ah/g_al.
// ---------------------------------------------------------------------------
__global__ void masked_softmax_split(const void* __restrict__ mask) {
    const int z = blockIdx.x;
    const int b = z / (NHEAD * S_LEN);
    const int s = z % S_LEN;
    const float* row = g_attn + (size_t)z * S_LEN;
    __nv_bfloat16* oh = g_ah + (size_t)z * S_LEN;
    __nv_bfloat16* ol = g_al + (size_t)z * S_LEN;
    const size_t mbase = (size_t)b * S_LEN * S_LEN + (size_t)s * S_LEN;
    const int kind = g_mask_kind;
    const int tid = threadIdx.x;

    float v[8];
    float mx = -3.0e38f;
#pragma unroll
    for (int i = 0; i < 8; i++) {
        const int tt = tid + i * 256;
        bool mk;
        if (kind == 1)      mk = ((const int*)mask)[mbase + tt] != 0;
        else if (kind == 2) mk = ((const float*)mask)[mbase + tt] != 0.0f;
        else                mk = ((const unsigned char*)mask)[mbase + tt] != 0;
        const float x = mk ? row[tt] : -1.0e9f;
        v[i] = x;
        mx = fmaxf(mx, x);
    }
    __shared__ float sm[256];
    sm[tid] = mx;
    __syncthreads();
    for (int o = 128; o > 0; o >>= 1) {
        if (tid < o) sm[tid] = fmaxf(sm[tid], sm[tid + o]);
        __syncthreads();
    }
    mx = sm[0];
    __syncthreads();
    float sum = 0.0f;
#pragma unroll
    for (int i = 0; i < 8; i++) {
        v[i] = __expf(v[i] - mx);
        sum += v[i];
    }
    sm[tid] = sum;
    __syncthreads();
    for (int o = 128; o > 0; o >>= 1) {
        if (tid < o) sm[tid] += sm[tid + o];
        __syncthreads();
    }
    const float inv = 1.0f / sm[0];
#pragma unroll
    for (int i = 0; i < 8; i++) {
        __nv_bfloat16 h, l;
        split2(v[i] * inv, h, l);
        oh[tid + i * 256] = h;
        ol[tid + i * 256] = l;
    }
}

// ---------------------------------------------------------------------------
// Launcher
// ---------------------------------------------------------------------------
static void* sym(const void* s) {
    void* p = nullptr;
    cudaGetSymbolAddress(&p, s);
    return p;
}

extern "C" void kernel_launch(void* const* d_in, const int* in_sizes, int n_in,
                              void* d_out, int out_size) {
    (void)in_sizes; (void)n_in; (void)out_size;

    const float* query = (const float*)d_in[0];
    const float* key   = (const float*)d_in[1];
    const float* value = (const float*)d_in[2];
    const void*  mask  = d_in[3];
    const float* Wq = (const float*)d_in[4];
    const float* bq = (const float*)d_in[5];
    const float* Wk = (const float*)d_in[6];
    const float* bk = (const float*)d_in[7];
    const float* Wv = (const float*)d_in[8];
    const float* bv = (const float*)d_in[9];
    const float* Wo = (const float*)d_in[10];
    const float* bo = (const float*)d_in[11];
    float* out = (float*)d_out;

    typedef __nv_bfloat16 bf;
    bf* xh0 = (bf*)sym(g_xh);                       bf* xl0 = (bf*)sym(g_xl);
    bf* xh1 = xh0 + (size_t)BATCH * S_LEN * DIM;    bf* xl1 = xl0 + (size_t)BATCH * S_LEN * DIM;
    bf* xh2 = xh1 + (size_t)BATCH * S_LEN * DIM;    bf* xl2 = xl1 + (size_t)BATCH * S_LEN * DIM;
    bf* wth0 = (bf*)sym(g_wth);                     bf* wtl0 = (bf*)sym(g_wtl);
    bf* wth1 = wth0 + (size_t)NHEAD * EDIM * DIM;   bf* wtl1 = wtl0 + (size_t)NHEAD * EDIM * DIM;
    bf* wth2 = wth1 + (size_t)NHEAD * EDIM * DIM;   bf* wtl2 = wtl1 + (size_t)NHEAD * EDIM * DIM;
    bf* woth = (bf*)sym(g_woth);  bf* wotl = (bf*)sym(g_wotl);
    bf* qh = (bf*)sym(g_qh);      bf* ql = (bf*)sym(g_ql);
    bf* kh = (bf*)sym(g_kh);      bf* kl = (bf*)sym(g_kl);
    bf* vth = (bf*)sym(g_vth);    bf* vtl = (bf*)sym(g_vtl);
    float* attn = (float*)sym(g_attn);
    bf* ah = (bf*)sym(g_ah);      bf* al = (bf*)sym(g_al);
    bf* cath = (bf*)sym(g_cath);  bf* catl = (bf*)sym(g_catl);

    cudaFuncSetAttribute(mm_hmma<0>, cudaFuncAttributeMaxDynamicSharedMemorySize, SMEM_DYN);
    cudaFuncSetAttribute(mm_hmma<1>, cudaFuncAttributeMaxDynamicSharedMemorySize, SMEM_DYN);
    cudaFuncSetAttribute(mm_hmma<2>, cudaFuncAttributeMaxDynamicSharedMemorySize, SMEM_DYN);

    const int BIG = 1 << 30;

    detect_mask_kind<<<1, 1>>>(mask);

    // --- input / weight split(+transpose) prep ---
    const int nX = BATCH * S_LEN * DIM;
    split_flat<<<(nX + 255) / 256, 256>>>(query, xh0, xl0, nX);
    split_flat<<<(nX + 255) / 256, 256>>>(key,   xh1, xl1, nX);
    split_flat<<<(nX + 255) / 256, 256>>>(value, xh2, xl2, nX);
    {
        dim3 g(EDIM / 32, DIM / 32, NHEAD), bdim(32, 8);
        split_T<<<g, bdim>>>(Wq, wth0, wtl0, DIM, EDIM);
        split_T<<<g, bdim>>>(Wk, wth1, wtl1, DIM, EDIM);
        split_T<<<g, bdim>>>(Wv, wth2, wtl2, DIM, EDIM);
    }
    {
        dim3 g(EDIM / 32, HE_DIM / 32, 1), bdim(32, 8);
        split_T<<<g, bdim>>>(Wo, woth, wotl, HE_DIM, EDIM);
    }

    // --- projections: X[s,d] @ W^T[e,d]^T -> [b,h,s,e] (v transposed) ---
    {
        dim3 grid(EDIM / TN, S_LEN / TM, BATCH * NHEAD);
        mm_hmma<1><<<grid, 256, SMEM_DYN>>>(
            xh0, xl0, (long)S_LEN * DIM, NHEAD, DIM,
            wth0, wtl0, (long)EDIM * DIM, NHEAD, DIM,
            bq, 1, qh, ql, (long)S_LEN * EDIM, 0, EDIM, DIM);
        mm_hmma<1><<<grid, 256, SMEM_DYN>>>(
            xh1, xl1, (long)S_LEN * DIM, NHEAD, DIM,
            wth1, wtl1, (long)EDIM * DIM, NHEAD, DIM,
            bk, 1, kh, kl, (long)S_LEN * EDIM, 0, EDIM, DIM);
        mm_hmma<2><<<grid, 256, SMEM_DYN>>>(
            xh2, xl2, (long)S_LEN * DIM, NHEAD, DIM,
            wth2, wtl2, (long)EDIM * DIM, NHEAD, DIM,
            bv, 1, vth, vtl, (long)EDIM * S_LEN, 0, S_LEN, DIM);
    }

    // --- scores: q[s,e] @ k[t,e]^T -> fp32 attn ---
    {
        dim3 grid(S_LEN / TN, S_LEN / TM, BATCH * NHEAD);
        mm_hmma<0><<<grid, 256, SMEM_DYN>>>(
            qh, ql, (long)S_LEN * EDIM, 1, EDIM,
            kh, kl, (long)S_LEN * EDIM, BIG, EDIM,
            nullptr, 0, attn, nullptr, (long)S_LEN * S_LEN, 0, S_LEN, EDIM);
    }

    // --- masked softmax -> split bf16 ---
    masked_softmax_split<<<BATCH * NHEAD * S_LEN, 256>>>(mask);

    // --- PV: attn[s,t] @ vT[e,t]^T -> cat[b,s,h*E+e] ---
    {
        dim3 grid(EDIM / TN, S_LEN / TM, BATCH * NHEAD);
        mm_hmma<1><<<grid, 256, SMEM_DYN>>>(
            ah, al, (long)S_LEN * S_LEN, 1, S_LEN,
            vth, vtl, (long)EDIM * S_LEN, BIG, S_LEN,
            nullptr, 0, cath, catl, 0L, 1, HE_DIM, S_LEN);
    }

    // --- output projection: cat[s,he] @ WoT[e,he]^T + bo -> out fp32 ---
    {
        dim3 grid(EDIM / TN, (BATCH * S_LEN) / 128, 1);
        mm_hmma<0><<<grid, 256, SMEM_DYN>>>(
            cath, catl, 0L, 1, HE_DIM,
            woth, wotl, 0L, 1, HE_DIM,
            bo, 2, out, nullptr, 0L, 0, EDIM, HE_DIM);
    }
}